// round 8
// baseline (speedup 1.0000x reference)
#include <cuda_runtime.h>
#include <cuda_bf16.h>

// Problem constants (fixed by the dataset)
#define BB   64
#define MM   64
#define NN   64
#define OUT  512

#define U_TILE      32
#define THREADS     128
#define V_PER_BLOCK 256   // 2 v per thread

typedef unsigned long long ull;

__device__ __forceinline__ ull pack2(float lo, float hi) {
    ull r; asm("mov.b64 %0, {%1, %2};" : "=l"(r) : "f"(lo), "f"(hi)); return r;
}
__device__ __forceinline__ float2 unpack2(ull p) {
    float2 v; asm("mov.b64 {%0, %1}, %2;" : "=f"(v.x), "=f"(v.y) : "l"(p)); return v;
}
__device__ __forceinline__ ull fma2(ull a, ull b, ull c) {
    ull d; asm("fma.rn.f32x2 %0, %1, %2, %3;" : "=l"(d) : "l"(a), "l"(b), "l"(c)); return d;
}
__device__ __forceinline__ ull mul2(ull a, ull b) {
    ull d; asm("mul.rn.f32x2 %0, %1, %2;" : "=l"(d) : "l"(a), "l"(b)); return d;
}
__device__ __forceinline__ ull add2(ull a, ull b) {
    ull d; asm("add.rn.f32x2 %0, %1, %2;" : "=l"(d) : "l"(a), "l"(b)); return d;
}

// ctrl float4 (x,y,z,w) as ulonglong2: .x = (x,y) pack, .y = (z,w) pack
__global__ __launch_bounds__(THREADS, 9) void surfeval_kernel(
    const ulonglong2* __restrict__ ctrl2,  // (B, M, N)
    const float4* __restrict__ Nu4,        // (OUT)
    const float4* __restrict__ Nv4,        // (OUT)
    const int* __restrict__ iu,            // (OUT,4) int32
    const int* __restrict__ iv,            // (OUT,4) int32
    float* __restrict__ out)               // (B, OUT, OUT, 3)
{
    __shared__ ull s_Nu[U_TILE][4];   // per-u splatted (nu.l, nu.l) pairs
    __shared__ int s_row0[U_TILE];

    const int tid = threadIdx.x;
    const int vt  = blockIdx.x;
    const int ut  = blockIdx.y;
    const int b   = blockIdx.z;

    const int u_lo = ut * U_TILE;
    const int u_hi = u_lo + U_TILE;

    if (tid < U_TILE) {
        const float4 nu = __ldg(&Nu4[u_lo + tid]);
        s_Nu[tid][0] = pack2(nu.x, nu.x);
        s_Nu[tid][1] = pack2(nu.y, nu.y);
        s_Nu[tid][2] = pack2(nu.z, nu.z);
        s_Nu[tid][3] = pack2(nu.w, nu.w);
        s_row0[tid]  = __ldg(&iu[(u_lo + tid) * 4]);
    }
    __syncthreads();

    const int v0 = vt * V_PER_BLOCK + 2 * tid;
    const float4 nva = __ldg(&Nv4[v0]);        // 8 scalar regs, packs built per span
    const float4 nvb = __ldg(&Nv4[v0 + 1]);
    const int iva = __ldg(&iv[v0 * 4]);
    const int ivb = __ldg(&iv[(v0 + 1) * 4]);

    const ulonglong2* ca  = ctrl2 + (size_t)b * MM * NN + iva;
    const ulonglong2* cbp = ctrl2 + (size_t)b * MM * NN + ivb;

    float* op = out + (((size_t)b * OUT + u_lo) * OUT + v0) * 3;
    const size_t ustride = (size_t)OUT * 3;

    int u = u_lo;
    #pragma unroll 1
    while (u < u_hi) {
        const int row0 = s_row0[u - u_lo];

        // rowdots for both v, packed (xy)/(zw); nv packs rebuilt here (short live range)
        ull rdaxy[4], rdazw[4], rdbxy[4], rdbzw[4];
        {
            const ull na0 = pack2(nva.x, nva.x), na1 = pack2(nva.y, nva.y);
            const ull na2 = pack2(nva.z, nva.z), na3 = pack2(nva.w, nva.w);
            const ull nb0 = pack2(nvb.x, nvb.x), nb1 = pack2(nvb.y, nvb.y);
            const ull nb2 = pack2(nvb.z, nvb.z), nb3 = pack2(nvb.w, nvb.w);

            const ulonglong2* pa = ca  + (size_t)row0 * NN;
            const ulonglong2* pb = cbp + (size_t)row0 * NN;
            #pragma unroll
            for (int l = 0; l < 4; ++l) {
                ulonglong2 c0 = pa[0], c1 = pa[1], c2 = pa[2], c3 = pa[3];
                rdaxy[l] = add2(fma2(na1, c1.x, mul2(na0, c0.x)),
                                fma2(na3, c3.x, mul2(na2, c2.x)));
                rdazw[l] = add2(fma2(na1, c1.y, mul2(na0, c0.y)),
                                fma2(na3, c3.y, mul2(na2, c2.y)));
                c0 = pb[0]; c1 = pb[1]; c2 = pb[2]; c3 = pb[3];
                rdbxy[l] = add2(fma2(nb1, c1.x, mul2(nb0, c0.x)),
                                fma2(nb3, c3.x, mul2(nb2, c2.x)));
                rdbzw[l] = add2(fma2(nb1, c1.y, mul2(nb0, c0.y)),
                                fma2(nb3, c3.y, mul2(nb2, c2.y)));
                pa += NN; pb += NN;
            }
        }

        // sweep all u sharing this span
        #pragma unroll 1
        do {
            const int uo = u - u_lo;
            const ull nx = s_Nu[uo][0], ny = s_Nu[uo][1];
            const ull nz = s_Nu[uo][2], nw = s_Nu[uo][3];

            // tree-form combine: depth 3 instead of 4
            const ull axy = add2(fma2(ny, rdaxy[1], mul2(nx, rdaxy[0])),
                                 fma2(nw, rdaxy[3], mul2(nz, rdaxy[2])));
            const ull azw = add2(fma2(ny, rdazw[1], mul2(nx, rdazw[0])),
                                 fma2(nw, rdazw[3], mul2(nz, rdazw[2])));
            const ull bxy = add2(fma2(ny, rdbxy[1], mul2(nx, rdbxy[0])),
                                 fma2(nw, rdbxy[3], mul2(nz, rdbxy[2])));
            const ull bzw = add2(fma2(ny, rdbzw[1], mul2(nx, rdbzw[0])),
                                 fma2(nw, rdbzw[3], mul2(nz, rdbzw[2])));

            const float2 zw0 = unpack2(azw);
            const float2 zw1 = unpack2(bzw);
            const float i0 = __fdividef(1.0f, zw0.y);
            const float i1 = __fdividef(1.0f, zw1.y);

            const ull  sxy0 = mul2(axy, pack2(i0, i0));
            const ull  sxy1 = mul2(bxy, pack2(i1, i1));
            const float z0  = zw0.x * i0;
            const float z1  = zw1.x * i1;
            const float2 s1 = unpack2(sxy1);

            ull* o64 = (ull*)op;
            o64[0] = sxy0;            // x0 y0
            o64[1] = pack2(z0, s1.x); // z0 x1
            o64[2] = pack2(s1.y, z1); // y1 z1

            op += ustride;
            ++u;
        } while (u < u_hi && s_row0[u - u_lo] == row0);
    }
}

extern "C" void kernel_launch(void* const* d_in, const int* in_sizes, int n_in,
                              void* d_out, int out_size) {
    const ulonglong2* ctrl = (const ulonglong2*)d_in[0];
    const float4*     Nu   = (const float4*)d_in[1];
    const float4*     Nv   = (const float4*)d_in[2];
    const int*        iu   = (const int*)d_in[3];
    const int*        iv   = (const int*)d_in[4];
    float*            out  = (float*)d_out;

    dim3 grid(OUT / V_PER_BLOCK, OUT / U_TILE, BB);   // (2, 16, 64) = 2048 CTAs
    surfeval_kernel<<<grid, THREADS>>>(ctrl, Nu, Nv, iu, iv, out);
}

// round 12
// speedup vs baseline: 1.0366x; 1.0366x over previous
#include <cuda_runtime.h>
#include <cuda_bf16.h>

// Problem constants (fixed by the dataset)
#define BB   64
#define MM   64   // ctrl rows (u direction)
#define NN   64   // ctrl cols (v direction)
#define OUT  512  // output grid per dim

#define U_TILE 16
#define V_TILE 128
#define THREADS 128

__global__ __launch_bounds__(THREADS, 12) void surfeval_kernel(
    const float4* __restrict__ ctrl4,   // (B, M, N) float4 (xyzw)
    const float4* __restrict__ Nu4,     // (OUT) float4
    const float4* __restrict__ Nv4,     // (OUT) float4
    const int* __restrict__ iu,         // (OUT,4) int32
    const int* __restrict__ iv,         // (OUT,4) int32
    float* __restrict__ out)            // (B, OUT, OUT, 3)
{
    __shared__ float4 s_Nu[U_TILE];
    __shared__ int    s_row0[U_TILE];

    const int tid  = threadIdx.x;
    const int vt   = blockIdx.x;          // v tile
    const int ut   = blockIdx.y;          // u tile
    const int b    = blockIdx.z;

    const int u_lo = ut * U_TILE;
    const int u_hi = u_lo + U_TILE;

    if (tid < U_TILE) {
        s_Nu[tid]   = __ldg(&Nu4[u_lo + tid]);
        s_row0[tid] = __ldg(&iu[(u_lo + tid) * 4]);
    }
    __syncthreads();

    const int v = vt * V_TILE + tid;
    const float4 nv = __ldg(&Nv4[v]);
    const int iv0 = __ldg(&iv[v * 4]);

    // base pointer for this batch, shifted to column iv0
    const float4* cb = ctrl4 + ((size_t)b * MM * NN) + iv0;

    // output pointer, incremented by one u-row per iteration
    float* op = out + (((size_t)b * OUT + u_lo) * OUT + v) * 3;
    const size_t u_stride = (size_t)OUT * 3;

    int u = u_lo;
    #pragma unroll 1
    while (u < u_hi) {
        const int row0 = s_row0[u - u_lo];

        // rowdot[l] = sum_r Nv[v,r] * ctrl[b, row0+l, iv0+r, :]
        float4 rd0, rd1, rd2, rd3;
        {
            const float4* p = cb + (size_t)row0 * NN;
            float4 c0 = p[0], c1 = p[1], c2 = p[2], c3 = p[3];
            rd0.x = nv.x*c0.x + nv.y*c1.x + nv.z*c2.x + nv.w*c3.x;
            rd0.y = nv.x*c0.y + nv.y*c1.y + nv.z*c2.y + nv.w*c3.y;
            rd0.z = nv.x*c0.z + nv.y*c1.z + nv.z*c2.z + nv.w*c3.z;
            rd0.w = nv.x*c0.w + nv.y*c1.w + nv.z*c2.w + nv.w*c3.w;
            p += NN;
            c0 = p[0]; c1 = p[1]; c2 = p[2]; c3 = p[3];
            rd1.x = nv.x*c0.x + nv.y*c1.x + nv.z*c2.x + nv.w*c3.x;
            rd1.y = nv.x*c0.y + nv.y*c1.y + nv.z*c2.y + nv.w*c3.y;
            rd1.z = nv.x*c0.z + nv.y*c1.z + nv.z*c2.z + nv.w*c3.z;
            rd1.w = nv.x*c0.w + nv.y*c1.w + nv.z*c2.w + nv.w*c3.w;
            p += NN;
            c0 = p[0]; c1 = p[1]; c2 = p[2]; c3 = p[3];
            rd2.x = nv.x*c0.x + nv.y*c1.x + nv.z*c2.x + nv.w*c3.x;
            rd2.y = nv.x*c0.y + nv.y*c1.y + nv.z*c2.y + nv.w*c3.y;
            rd2.z = nv.x*c0.z + nv.y*c1.z + nv.z*c2.z + nv.w*c3.z;
            rd2.w = nv.x*c0.w + nv.y*c1.w + nv.z*c2.w + nv.w*c3.w;
            p += NN;
            c0 = p[0]; c1 = p[1]; c2 = p[2]; c3 = p[3];
            rd3.x = nv.x*c0.x + nv.y*c1.x + nv.z*c2.x + nv.w*c3.x;
            rd3.y = nv.x*c0.y + nv.y*c1.y + nv.z*c2.y + nv.w*c3.y;
            rd3.z = nv.x*c0.z + nv.y*c1.z + nv.z*c2.z + nv.w*c3.z;
            rd3.w = nv.x*c0.w + nv.y*c1.w + nv.z*c2.w + nv.w*c3.w;
        }

        // sweep all u sharing this span (same row0; uniform across warp)
        #pragma unroll 1
        do {
            const float4 nu = s_Nu[u - u_lo];
            float4 acc;
            acc.x = nu.x*rd0.x + nu.y*rd1.x + nu.z*rd2.x + nu.w*rd3.x;
            acc.y = nu.x*rd0.y + nu.y*rd1.y + nu.z*rd2.y + nu.w*rd3.y;
            acc.z = nu.x*rd0.z + nu.y*rd1.z + nu.z*rd2.z + nu.w*rd3.z;
            acc.w = nu.x*rd0.w + nu.y*rd1.w + nu.z*rd2.w + nu.w*rd3.w;

            const float inv = __fdividef(1.0f, acc.w);
            op[0] = acc.x * inv;
            op[1] = acc.y * inv;
            op[2] = acc.z * inv;
            op += u_stride;
            ++u;
        } while (u < u_hi && s_row0[u - u_lo] == row0);
    }
}

extern "C" void kernel_launch(void* const* d_in, const int* in_sizes, int n_in,
                              void* d_out, int out_size) {
    const float4* ctrl = (const float4*)d_in[0];
    const float4* Nu   = (const float4*)d_in[1];
    const float4* Nv   = (const float4*)d_in[2];
    const int*    iu   = (const int*)d_in[3];
    const int*    iv   = (const int*)d_in[4];
    float*        out  = (float*)d_out;

    dim3 grid(OUT / V_TILE, OUT / U_TILE, BB);   // (4, 32, 64) = 8192 CTAs
    surfeval_kernel<<<grid, THREADS>>>(ctrl, Nu, Nv, iu, iv, out);
}